// round 13
// baseline (speedup 1.0000x reference)
#include <cuda_runtime.h>
#include <math.h>

#define NS 131072           // N_SAMPLES
#define NEV 64              // B*E
#define MF 262144           // FFT length = 2*NS
#define NFRAMES 128
#define CPD 16
#define SP 588              // FFT smem buffer stride (conflict-free: 588%32=12)

struct EvScalars { int vidx; int ridx; float av0; float av1; };

__device__ EvScalars g_sc[NEV];
__device__ unsigned  g_normbits[NEV];   // max |mixed|
__device__ unsigned  g_hmaxbits[NEV];   // max |h|
__device__ int       g_vcount[8];       // events per verb
__device__ int       g_vlist[8 * 64];   // event ids grouped by verb
__device__ float     g_cpw[NEV * 3 * CPD * NFRAMES];   // smix-weighted cp_out
__device__ float     g_mixed[NEV * NS];
__device__ float     g_h[NEV * NS];
__device__ float2    g_twA[512];        // W_512^a = W_MF^(512a)
__device__ float2    g_twB[512];        // W_MF^b
// zA: forward pass-1 output (64 slots: 32 m-pairs, 32 h-pairs).
// zB: inverse pass-1 output (32 slots), layout [k*512 + n1].
__device__ float2    g_zA[NEV * MF];
__device__ float2    g_zB[NEV * MF];

__device__ __forceinline__ float2 cmul(float2 a, float2 b) {
    return make_float2(a.x * b.x - a.y * b.y, a.x * b.y + a.y * b.x);
}
__device__ __forceinline__ float2 cadd(float2 a, float2 b){return make_float2(a.x+b.x,a.y+b.y);}
__device__ __forceinline__ float2 csub(float2 a, float2 b){return make_float2(a.x-b.x,a.y-b.y);}

template<bool INV>
__device__ __forceinline__ float2 mulj(float2 a) {  // * (-i) fwd, * (+i) inv
    return INV ? make_float2(-a.y, a.x) : make_float2(a.y, -a.x);
}

// 8-point DFT, natural-order in/out
template<bool INV>
__device__ __forceinline__ void dft8(float2 v[8]) {
    const float C = 0.70710678118654752f;
    float2 b0=cadd(v[0],v[4]), b4=csub(v[0],v[4]);
    float2 b1=cadd(v[1],v[5]), b5=csub(v[1],v[5]);
    float2 b2=cadd(v[2],v[6]), b6=csub(v[2],v[6]);
    float2 b3=cadd(v[3],v[7]), b7=csub(v[3],v[7]);
    b5 = INV ? make_float2(C*(b5.x-b5.y), C*(b5.x+b5.y))
             : make_float2(C*(b5.x+b5.y), C*(b5.y-b5.x));
    b6 = mulj<INV>(b6);
    b7 = INV ? make_float2(-C*(b7.x+b7.y), C*(b7.x-b7.y))
             : make_float2(C*(b7.y-b7.x), -C*(b7.x+b7.y));
    float2 c0=cadd(b0,b2), c2=csub(b0,b2);
    float2 c1=cadd(b1,b3), c3=mulj<INV>(csub(b1,b3));
    float2 c4=cadd(b4,b6), c6=csub(b4,b6);
    float2 c5=cadd(b5,b7), c7=mulj<INV>(csub(b5,b7));
    v[0]=cadd(c0,c1); v[4]=csub(c0,c1);
    v[2]=cadd(c2,c3); v[6]=csub(c2,c3);
    v[1]=cadd(c4,c5); v[5]=csub(c4,c5);
    v[3]=cadd(c6,c7); v[7]=csub(c6,c7);
}

// 8-point DFT with v[4..7] == 0 implicitly (zero-padded upper half). Exact.
template<bool INV>
__device__ __forceinline__ void dft8h(float2 v[8]) {
    const float C = 0.70710678118654752f;
    float2 b0=v[0], b4=v[0];
    float2 b1=v[1], b5=v[1];
    float2 b2=v[2], b6=v[2];
    float2 b3=v[3], b7=v[3];
    b5 = INV ? make_float2(C*(b5.x-b5.y), C*(b5.x+b5.y))
             : make_float2(C*(b5.x+b5.y), C*(b5.y-b5.x));
    b6 = mulj<INV>(b6);
    b7 = INV ? make_float2(-C*(b7.x+b7.y), C*(b7.x-b7.y))
             : make_float2(C*(b7.y-b7.x), -C*(b7.x+b7.y));
    float2 c0=cadd(b0,b2), c2=csub(b0,b2);
    float2 c1=cadd(b1,b3), c3=mulj<INV>(csub(b1,b3));
    float2 c4=cadd(b4,b6), c6=csub(b4,b6);
    float2 c5=cadd(b5,b7), c7=mulj<INV>(csub(b5,b7));
    v[0]=cadd(c0,c1); v[4]=csub(c0,c1);
    v[2]=cadd(c2,c3); v[6]=csub(c2,c3);
    v[1]=cadd(c4,c5); v[5]=csub(c4,c5);
    v[3]=cadd(c6,c7); v[7]=csub(c6,c7);
}

// ---------------------------------------------------------------------------
// 512-point FFT, radix-8^3, 64 threads per FFT (8 FFTs per 512-thread CTA).
// HALF: input positions 256..511 are zero. HOUT: only outputs k<256 stored.
// ---------------------------------------------------------------------------
template<bool INV, bool HALF, bool HOUT>
__device__ __forceinline__ void fft512(float* sRe, float* sIm, const float2* sW, int tid) {
    int t = tid & 63;
    int base = (tid >> 6) * SP;
    float2 v[8];
    if (HALF) {
#pragma unroll
        for (int j = 0; j < 4; j++) {
            int a = base + t + 64 * j;
            v[j] = make_float2(sRe[a], sIm[a]);
        }
        dft8h<INV>(v);
    } else {
#pragma unroll
        for (int j = 0; j < 8; j++) {
            int a = base + t + 64 * j;
            v[j] = make_float2(sRe[a], sIm[a]);
        }
        dft8<INV>(v);
    }
    {
        float2 w1 = sW[t];                 // W_512^t
        if (INV) w1.y = -w1.y;
        float2 wc = w1;
        v[1] = cmul(v[1], wc);
#pragma unroll
        for (int k0 = 2; k0 < 8; k0++) { wc = cmul(wc, w1); v[k0] = cmul(v[k0], wc); }
    }
    __syncthreads();
#pragma unroll
    for (int k0 = 0; k0 < 8; k0++) {
        int a = base + 72 * k0 + t;
        sRe[a] = v[k0].x; sIm[a] = v[k0].y;
    }
    __syncthreads();
    int k0 = t >> 3, r = t & 7;
#pragma unroll
    for (int m1 = 0; m1 < 8; m1++) {
        int a = base + 72 * k0 + r + 8 * m1;
        v[m1] = make_float2(sRe[a], sIm[a]);
    }
    dft8<INV>(v);
    {
        float2 w1 = sW[8 * r];             // W_64^r
        if (INV) w1.y = -w1.y;
        float2 wc = w1;
        v[1] = cmul(v[1], wc);
#pragma unroll
        for (int k1 = 2; k1 < 8; k1++) { wc = cmul(wc, w1); v[k1] = cmul(v[k1], wc); }
    }
    __syncthreads();
#pragma unroll
    for (int k1 = 0; k1 < 8; k1++) {
        int a = base + 72 * k0 + 9 * k1 + r;
        sRe[a] = v[k1].x; sIm[a] = v[k1].y;
    }
    __syncthreads();
#pragma unroll
    for (int m0 = 0; m0 < 8; m0++) {
        int a = base + 72 * k0 + 9 * r + m0;
        v[m0] = make_float2(sRe[a], sIm[a]);
    }
    dft8<INV>(v);
    __syncthreads();
#pragma unroll
    for (int k2 = 0; k2 < (HOUT ? 4 : 8); k2++) {
        int a = base + k0 + 8 * r + 64 * k2;
        sRe[a] = v[k2].x; sIm[a] = v[k2].y;
    }
    __syncthreads();
}

// ---------------------------------------------------------------------------
__global__ void k_tw1() {
    int t = threadIdx.x;   // 512
    double s, c;
    double angA = -2.0 * 3.14159265358979323846 * (double)t / 512.0;
    sincos(angA, &s, &c);
    g_twA[t] = make_float2((float)c, (float)s);
    double angB = -2.0 * 3.14159265358979323846 * (double)t / (double)MF;
    sincos(angB, &s, &c);
    g_twB[t] = make_float2((float)c, (float)s);
    if (t < 8) g_vcount[t] = 0;
}

// ---------------------------------------------------------------------------
// Per-event prep: argmaxes, softmaxes, cp select + sparsify (radix select),
// 3-block stack.
// ---------------------------------------------------------------------------
__global__ void k_prep(const float* __restrict__ voice, const float* __restrict__ cpc,
                       const float* __restrict__ amp,   const float* __restrict__ rooml,
                       const float* __restrict__ rmix,  const float* __restrict__ cp_items,
                       const float* __restrict__ w1,    const float* __restrict__ w2,
                       const float* __restrict__ decays,const float* __restrict__ gains,
                       const float* __restrict__ mix) {
    int e = blockIdx.x, tid = threadIdx.x;
    __shared__ float s_cp[2048];
    __shared__ float s_wc[2048];
    __shared__ float s_x[2048];
    __shared__ float s_y[2048];
    __shared__ float s_w1[256], s_w2[256];
    __shared__ float s_d[16], s_g[16];
    __shared__ float s_red[256];
    __shared__ float s_smix[3];
    __shared__ int   s_vidx, s_cidx;
    __shared__ int   s_hist[256];
    __shared__ unsigned s_pref;
    __shared__ int   s_rem;

    if (tid == 0) {
        const float* v = voice + e * 8;
        int vi = 0; float bv = v[0];
        for (int i = 1; i < 8; i++) if (v[i] > bv) { bv = v[i]; vi = i; }
        s_vidx = vi;
        const float* c = cpc + e * 512;
        int ci = 0; float bc = c[0];
        for (int i = 1; i < 512; i++) if (c[i] > bc) { bc = c[i]; ci = i; }
        s_cidx = ci;
        const float* r = rooml + e * 8;
        int ri = 0; float br = r[0];
        for (int i = 1; i < 8; i++) if (r[i] > br) { br = r[i]; ri = i; }
        float m0 = rmix[e * 2 + 0], m1 = rmix[e * 2 + 1];
        float mx = fmaxf(m0, m1);
        float e0 = expf(m0 - mx), e1 = expf(m1 - mx);
        float vm0 = e0 / (e0 + e1), vm1 = e1 / (e0 + e1);
        float a = fabsf(amp[e]);
        g_sc[e].vidx = vi; g_sc[e].ridx = ri;
        g_sc[e].av0 = a * vm0; g_sc[e].av1 = a * vm1;
        int pos = atomicAdd(&g_vcount[ri], 1);
        g_vlist[ri * 64 + pos] = e;
        float q0 = mix[vi * 3 + 0], q1 = mix[vi * 3 + 1], q2 = mix[vi * 3 + 2];
        float qm = fmaxf(q0, fmaxf(q1, q2));
        float f0 = expf(q0 - qm), f1 = expf(q1 - qm), f2 = expf(q2 - qm);
        float fs = f0 + f1 + f2;
        s_smix[0] = f0 / fs; s_smix[1] = f1 / fs; s_smix[2] = f2 / fs;
        g_normbits[e] = 0u;
        g_hmaxbits[e] = 0u;
        s_pref = 0u; s_rem = 31;
    }
    __syncthreads();
    int vi = s_vidx, ci = s_cidx;

    float ls = 0.f;
    for (int i = tid; i < 2048; i += 256) {
        float v = cp_items[ci * 2048 + i];
        s_cp[i] = v; ls += v;
    }
    s_red[tid] = ls; __syncthreads();
    for (int o = 128; o > 0; o >>= 1) {
        if (tid < o) s_red[tid] += s_red[tid + o];
        __syncthreads();
    }
    float inv = 1.0f / (s_red[0] + 1e-8f);

    // Radix-select V32 = 32nd-largest value (uint keys monotone; values > 0).
    float vloc[8]; unsigned keys[8];
#pragma unroll
    for (int u = 0; u < 8; u++) {
        vloc[u] = s_cp[tid + 256 * u];
        keys[u] = __float_as_uint(vloc[u]);
    }
#pragma unroll
    for (int pass = 0; pass < 4; pass++) {
        int shift = 24 - 8 * pass;
        unsigned mhi = (pass == 0) ? 0u : (0xFFFFFFFFu << (32 - 8 * pass));
        s_hist[tid] = 0;
        __syncthreads();
        unsigned pref = s_pref;
#pragma unroll
        for (int u = 0; u < 8; u++)
            if ((keys[u] & mhi) == pref)
                atomicAdd(&s_hist[(keys[u] >> shift) & 0xFF], 1);
        __syncthreads();
        int rem = s_rem;
        int above = 0;
        for (int b = tid + 1; b < 256; b++) above += s_hist[b];
        if (above <= rem && rem < above + s_hist[tid]) {
            s_pref = pref | ((unsigned)tid << shift);
            s_rem = rem - above;
        }
        __syncthreads();
    }
    unsigned kth = s_pref;
#pragma unroll
    for (int u = 0; u < 8; u++)
        s_wc[tid + 256 * u] = (keys[u] >= kth) ? vloc[u] * inv : 0.f;
    __syncthreads();

    for (int blk = 0; blk < 3; blk++) {
        s_w1[tid] = w1[(vi * 3 + blk) * 256 + tid];
        s_w2[tid] = w2[(vi * 3 + blk) * 256 + tid];
        if (tid < 16) {
            float dp = decays[(vi * 3 + blk) * 16 + tid];
            s_d[tid] = 0.5f + (1.f / (1.f + expf(-dp))) * 0.5f;
            float gp = gains[(vi * 3 + blk) * 16 + tid];
            s_g[tid] = (1.f / (1.f + expf(-gp))) * 5.f;
        }
        __syncthreads();
#pragma unroll
        for (int u = 0; u < 8; u++) {
            int idx = tid + 256 * u;
            int c = idx >> 7, f = idx & 127;
            float acc = 0.f;
#pragma unroll
            for (int k = 0; k < 16; k++)
                acc += s_w1[c * 16 + k] * fmaxf(s_wc[k * 128 + f], 0.f);
            s_x[idx] = acc;
        }
        __syncthreads();
        if (tid < 16) {
            float d = s_d[tid];
            float y = 0.f;
            for (int f = 0; f < 128; f++) {
                y = d * (s_x[tid * 128 + f] + y);
                s_y[tid * 128 + f] = y;
            }
        }
        __syncthreads();
#pragma unroll
        for (int u = 0; u < 8; u++) {
            int idx = tid + 256 * u;
            int c = idx >> 7, f = idx & 127;
            float acc = s_x[idx];
#pragma unroll
            for (int k = 0; k < 16; k++)
                acc += s_w2[c * 16 + k] * s_y[k * 128 + f];
            float co = tanhf(acc * s_g[c]);
            g_cpw[((e * 3 + blk) * 16 + c) * 128 + f] = s_smix[blk] * co;
            s_wc[idx] = co;
        }
        __syncthreads();
    }
}

// ---------------------------------------------------------------------------
// MERGED audio-synthesis + h-computation kernel (flat grid, 3072 blocks).
//   bid < 1024 : h path (chunk = bid&127, verb = bid>>7)
//   bid >= 1024: audio path: wc = b&1, fg = (b>>1)&15, e = b>>5 (b=bid-1024)
// Audio q reduced 4->2 and blocks doubled for occupancy (latency-bound).
// ---------------------------------------------------------------------------
__global__ void __launch_bounds__(256, 4) k_ah(const float* __restrict__ audio_maps,
                                               const float* __restrict__ verbs,
                                               const float* __restrict__ times) {
    int bid = blockIdx.x, tid = threadIdx.x;
    __shared__ float s_c[8][48];
    __shared__ float s_red[256];
    __shared__ int s_v;
    __shared__ float s_t[8][128];
    __shared__ int   s_ei[8];
    __shared__ float s_av0[8], s_av1[8];
    __shared__ float s_wm[8][8];

    if (bid < 1024) {
        // ------------- h path -------------
        int chunk = bid & 127, r = bid >> 7;
        int cnt = g_vcount[r];
        if (cnt == 0) return;
        int t0 = chunk << 10;
        const float* vb = verbs + (size_t)r * NS;

        for (int b = 0; b < cnt; b += 8) {
            int nb = min(8, cnt - b);
            if (tid < 8) {
                if (tid < nb) {
                    int e = g_vlist[r * 64 + b + tid];
                    s_ei[tid] = e;
                    s_av0[tid] = g_sc[e].av0;
                    s_av1[tid] = g_sc[e].av1;
                } else s_ei[tid] = -1;
            }
            __syncthreads();
            for (int s = tid; s < 1024; s += 256) {
                int i = s >> 7, f = s & 127;
                s_t[i][f] = (i < nb) ? times[(size_t)g_vlist[r * 64 + b + i] * 128 + f] : 0.f;
            }
            __syncthreads();

            float4 acc[8];
#pragma unroll
            for (int i = 0; i < 8; i++) acc[i] = make_float4(0.f, 0.f, 0.f, 0.f);
            const float4* vbase = reinterpret_cast<const float4*>(vb + t0) + tid;
#pragma unroll 2
            for (int f = 0; f <= chunk; f++) {
                float4 v = vbase[-(f << 8)];
#pragma unroll
                for (int i = 0; i < 8; i++) {
                    float tf = s_t[i][f];
                    acc[i].x += v.x * tf; acc[i].y += v.y * tf;
                    acc[i].z += v.z * tf; acc[i].w += v.w * tf;
                }
            }

            float lm[8];
#pragma unroll
            for (int i = 0; i < 8; i++) lm[i] = 0.f;
            for (int i = 0; i < nb; i++) {
                float a0 = s_av0[i];
                float4 val = make_float4(a0 * acc[i].x, a0 * acc[i].y,
                                         a0 * acc[i].z, a0 * acc[i].w);
                if (tid == 0) val.x += s_av1[i] * s_t[i][chunk];
                reinterpret_cast<float4*>(g_h + (size_t)s_ei[i] * NS + t0)[tid] = val;
                lm[i] = fmaxf(fmaxf(fabsf(val.x), fabsf(val.y)),
                              fmaxf(fabsf(val.z), fabsf(val.w)));
            }
#pragma unroll
            for (int i = 0; i < 8; i++) {
#pragma unroll
                for (int off = 16; off; off >>= 1)
                    lm[i] = fmaxf(lm[i], __shfl_xor_sync(0xffffffffu, lm[i], off));
            }
            int wid = tid >> 5, lane = tid & 31;
            if (lane == 0) {
#pragma unroll
                for (int i = 0; i < 8; i++) s_wm[wid][i] = lm[i];
            }
            __syncthreads();
            if (tid < 8) {
                float m = s_wm[0][tid];
#pragma unroll
                for (int w = 1; w < 8; w++) m = fmaxf(m, s_wm[w][tid]);
                if (tid < nb) atomicMax(&g_hmaxbits[s_ei[tid]], __float_as_uint(m));
            }
            __syncthreads();
        }
    } else {
        // ------------- audio path -------------
        int b2 = bid - 1024;
        int wc = b2 & 1, fg = (b2 >> 1) & 15, e = b2 >> 5;
        int w0 = wc * 512 + tid;
        if (tid == 0) s_v = g_sc[e].vidx;
        for (int s = tid; s < 384; s += 256) {
            int fr = s / 48, ic = s % 48;
            int i = ic >> 4, c = ic & 15;
            s_c[fr][ic] = g_cpw[((e * 3 + i) * 16 + c) * 128 + (fg * 8 + fr)];
        }
        __syncthreads();
        const float* am = audio_maps + (size_t)s_v * 3 * 1024 * 16;
        float acc[8][2];
#pragma unroll
        for (int fr = 0; fr < 8; fr++)
#pragma unroll
            for (int q = 0; q < 2; q++) acc[fr][q] = 0.f;

#pragma unroll
        for (int i = 0; i < 3; i++) {
#pragma unroll
            for (int r = 0; r < 4; r++) {
                float4 a[2];
#pragma unroll
                for (int q = 0; q < 2; q++)
                    a[q] = __ldg(reinterpret_cast<const float4*>(
                               am + (i * 1024 + w0 + 256 * q) * 16) + r);
#pragma unroll
                for (int fr = 0; fr < 8; fr++) {
                    float c0 = s_c[fr][i * 16 + 4 * r + 0];
                    float c1 = s_c[fr][i * 16 + 4 * r + 1];
                    float c2 = s_c[fr][i * 16 + 4 * r + 2];
                    float c3 = s_c[fr][i * 16 + 4 * r + 3];
#pragma unroll
                    for (int q = 0; q < 2; q++)
                        acc[fr][q] += a[q].x * c0 + a[q].y * c1 + a[q].z * c2 + a[q].w * c3;
                }
            }
        }
        float lmax = 0.f;
#pragma unroll
        for (int fr = 0; fr < 8; fr++) {
#pragma unroll
            for (int q = 0; q < 2; q++) {
                float v = acc[fr][q];
                g_mixed[e * NS + (fg * 8 + fr) * 1024 + w0 + 256 * q] = v;
                lmax = fmaxf(lmax, fabsf(v));
            }
        }
        s_red[tid] = lmax; __syncthreads();
        for (int o = 128; o > 0; o >>= 1) {
            if (tid < o) s_red[tid] = fmaxf(s_red[tid], s_red[tid + o]);
            __syncthreads();
        }
        if (tid == 0) atomicMax(&g_normbits[e], __float_as_uint(s_red[0]));
    }
}

// ---------------------------------------------------------------------------
// FFT passes. MODE 0: fwd pass1 (64 slots) -> zA (HALF: zero-padded top).
// MODE 3: inv pass2 + epilogue (HOUT: only k<256 outputs stored/needed).
// ---------------------------------------------------------------------------
template <int MODE>
__global__ void __launch_bounds__(512) k_fft2(float* __restrict__ out) {
    __shared__ float sRe[8 * SP];
    __shared__ float sIm[8 * SP];
    __shared__ float2 sW[512];
    __shared__ float2 sWB[512];
    int slot = blockIdx.y, tile = blockIdx.x, tid = threadIdx.x;
    int c0 = tile * 8;
    const bool INV = (MODE >= 2);

    sW[tid] = g_twA[tid];
    if (MODE == 0) sWB[tid] = g_twB[tid];

    if (MODE == 0) {
        const float *s1, *s2;
        float f1, f2;
        if (slot < 32) {
            int e1 = 2 * slot, e2 = 2 * slot + 1;
            s1 = g_mixed + (size_t)e1 * NS;
            s2 = g_mixed + (size_t)e2 * NS;
            f1 = 1.0f / (__uint_as_float(g_normbits[e1]) + 1e-8f);
            f2 = 1.0f / (__uint_as_float(g_normbits[e2]) + 1e-8f);
        } else {
            int e1 = 2 * (slot - 32), e2 = e1 + 1;
            s1 = g_h + (size_t)e1 * NS;
            s2 = g_h + (size_t)e2 * NS;
            f1 = 1.0f / (__uint_as_float(g_hmaxbits[e1]) + 1e-20f);
            f2 = 1.0f / (__uint_as_float(g_hmaxbits[e2]) + 1e-20f);
        }
#pragma unroll
        for (int it = 0; it < 4; it++) {
            int lin = tid + 512 * it;
            int f = lin & 7, r = lin >> 3;          // r < 256
            int n = c0 + f + 512 * r;               // n < NS always
            sRe[f * SP + r] = s1[n] * f1;
            sIm[f * SP + r] = s2[n] * f2;
        }
    } else {   // MODE 3: rows of zB, contiguous
#pragma unroll
        for (int it = 0; it < 8; it++) {
            int lin = tid + 512 * it;
            int f = lin >> 9, n1 = lin & 511;
            float2 z = g_zB[(size_t)slot * MF + (c0 + f) * 512 + n1];
            sRe[f * SP + n1] = z.x; sIm[f * SP + n1] = z.y;
        }
    }
    __syncthreads();

    fft512<INV, MODE == 0, MODE == 3>(sRe, sIm, sW, tid);

    if (MODE == 0) {
        int f = tid & 7, k0 = tid >> 3;
        int n1 = c0 + f;
        int pb = n1 * k0;
        int ps = n1 * 64;
        float2 w  = cmul(sW[pb >> 9], sWB[pb & 511]);   // W_MF^(n1*k0)
        float2 st = cmul(sW[ps >> 9], sWB[ps & 511]);   // W_MF^(n1*64)
#pragma unroll
        for (int it = 0; it < 8; it++) {
            int k = k0 + 64 * it;
            float2 v = make_float2(sRe[f * SP + k], sIm[f * SP + k]);
            g_zA[(size_t)slot * MF + k * 512 + n1] = cmul(v, w);
            w = cmul(w, st);
        }
    } else {
        int e1 = 2 * slot, e2 = 2 * slot + 1;
        const float invm = 1.0f / (float)MF;
        float sc1 = (__uint_as_float(g_hmaxbits[e1]) + 1e-20f) * invm;
        float sc2 = (__uint_as_float(g_hmaxbits[e2]) + 1e-20f) * invm;
        float* o1 = out + (size_t)e1 * NS;
        float* o2 = out + (size_t)e2 * NS;
#pragma unroll
        for (int it = 0; it < 4; it++) {   // only k < 256 -> t < NS
            int lin = tid + 512 * it;
            int f = lin & 7, k = lin >> 3;
            int t = (c0 + f) + 512 * k;
            o1[t] = sRe[f * SP + k] * sc1;
            o2[t] = sIm[f * SP + k] * sc2;
        }
    }
}

// ---------------------------------------------------------------------------
// Fused forward pass-2 + combine + INVERSE pass-1 (SP pad, staged twB).
// ---------------------------------------------------------------------------
__device__ __forceinline__ float2 ldbuf(const float* sRe, const float* sIm, int i, int k) {
    return make_float2(sRe[i * SP + k], sIm[i * SP + k]);
}
__device__ __forceinline__ void stbuf(float* sRe, float* sIm, int i, int k, float2 v) {
    sRe[i * SP + k] = v.x; sIm[i * SP + k] = v.y;
}

__global__ void __launch_bounds__(512, 2) k_fc2() {
    __shared__ float sRe[8 * SP];
    __shared__ float sIm[8 * SP];
    __shared__ float2 sW[512];
    __shared__ float2 sWB[512];
    int p = blockIdx.y, T = blockIdx.x, tid = threadIdx.x;
    sW[tid] = g_twA[tid];
    sWB[tid] = g_twB[tid];

    float2 park[8];

#pragma unroll
    for (int half = 0; half < 2; half++) {
        int t = 2 * T + half;
        int rows4[4];
        if (t == 0) { rows4[0] = 0; rows4[1] = 256; rows4[2] = 1; rows4[3] = 511; }
        else { rows4[0] = 2 * t; rows4[1] = 512 - 2 * t;
               rows4[2] = 2 * t + 1; rows4[3] = 511 - 2 * t; }
        if (half) __syncthreads();    // half0 product reads complete before overwrite
#pragma unroll
        for (int it = 0; it < 8; it++) {
            int sl = (it < 4) ? p : (32 + p);
            float2 z = g_zA[(size_t)sl * MF + rows4[it & 3] * 512 + tid];
            sRe[it * SP + tid] = z.x; sIm[it * SP + tid] = z.y;
        }
        __syncthreads();

        fft512<false, false, false>(sRe, sIm, sW, tid);

        int o = half * 4;
        if (t == 0) {
            {   // row 0 (self-mirror: col (512-k2)&511)
                int kp = (512 - tid) & 511;
                float2 Za = ldbuf(sRe, sIm, 0, tid), Zb = ldbuf(sRe, sIm, 0, kp);
                float2 Ha = ldbuf(sRe, sIm, 4, tid), Hb = ldbuf(sRe, sIm, 4, kp);
                float2 M1 = make_float2(0.5f*(Za.x+Zb.x), 0.5f*(Za.y-Zb.y));
                float2 M2 = make_float2(0.5f*(Za.y+Zb.y), 0.5f*(Zb.x-Za.x));
                float2 H1 = make_float2(0.5f*(Ha.x+Hb.x), 0.5f*(Ha.y-Hb.y));
                float2 H2 = make_float2(0.5f*(Ha.y+Hb.y), 0.5f*(Hb.x-Ha.x));
                float2 P1 = cmul(M1, H1), P2 = cmul(M2, H2);
                park[o + 0] = make_float2(P1.x - P2.y, P1.y + P2.x);   // row 0 @ tid
            }
            {   // row 256 (self-mirror: col 511-k2)
                int kp = 511 - tid;
                float2 Za = ldbuf(sRe, sIm, 1, tid), Zb = ldbuf(sRe, sIm, 1, kp);
                float2 Ha = ldbuf(sRe, sIm, 5, tid), Hb = ldbuf(sRe, sIm, 5, kp);
                float2 M1 = make_float2(0.5f*(Za.x+Zb.x), 0.5f*(Za.y-Zb.y));
                float2 M2 = make_float2(0.5f*(Za.y+Zb.y), 0.5f*(Zb.x-Za.x));
                float2 H1 = make_float2(0.5f*(Ha.x+Hb.x), 0.5f*(Ha.y-Hb.y));
                float2 H2 = make_float2(0.5f*(Ha.y+Hb.y), 0.5f*(Hb.x-Ha.x));
                float2 P1 = cmul(M1, H1), P2 = cmul(M2, H2);
                park[o + 1] = make_float2(P1.x - P2.y, P1.y + P2.x);   // row 256 @ tid
            }
            {   // pair (1, 511)
                int kp = 511 - tid;
                float2 Za = ldbuf(sRe, sIm, 2, tid), Zb = ldbuf(sRe, sIm, 3, kp);
                float2 Ha = ldbuf(sRe, sIm, 6, tid), Hb = ldbuf(sRe, sIm, 7, kp);
                float2 M1 = make_float2(0.5f*(Za.x+Zb.x), 0.5f*(Za.y-Zb.y));
                float2 M2 = make_float2(0.5f*(Za.y+Zb.y), 0.5f*(Zb.x-Za.x));
                float2 H1 = make_float2(0.5f*(Ha.x+Hb.x), 0.5f*(Ha.y-Hb.y));
                float2 H2 = make_float2(0.5f*(Ha.y+Hb.y), 0.5f*(Hb.x-Ha.x));
                float2 P1 = cmul(M1, H1), P2 = cmul(M2, H2);
                park[o + 2] = make_float2(P1.x - P2.y, P1.y + P2.x);   // row 1 @ tid
                park[o + 3] = make_float2(P1.x + P2.y, P2.x - P1.y);   // row 511 @ 511-tid
            }
        } else {
#pragma unroll
            for (int pr = 0; pr < 2; pr++) {
                int ia = 2 * pr, ib = 2 * pr + 1;
                int kp = 511 - tid;
                float2 Za = ldbuf(sRe, sIm, ia, tid), Zb = ldbuf(sRe, sIm, ib, kp);
                float2 Ha = ldbuf(sRe, sIm, ia + 4, tid), Hb = ldbuf(sRe, sIm, ib + 4, kp);
                float2 M1 = make_float2(0.5f*(Za.x+Zb.x), 0.5f*(Za.y-Zb.y));
                float2 M2 = make_float2(0.5f*(Za.y+Zb.y), 0.5f*(Zb.x-Za.x));
                float2 H1 = make_float2(0.5f*(Ha.x+Hb.x), 0.5f*(Ha.y-Hb.y));
                float2 H2 = make_float2(0.5f*(Ha.y+Hb.y), 0.5f*(Hb.x-Ha.x));
                float2 P1 = cmul(M1, H1), P2 = cmul(M2, H2);
                park[o + 2 * pr + 0] = make_float2(P1.x - P2.y, P1.y + P2.x);  // rows4[ia] @ tid
                park[o + 2 * pr + 1] = make_float2(P1.x + P2.y, P2.x - P1.y);  // rows4[ib] @ 511-tid
            }
        }
    }
    __syncthreads();   // all product reads done before buffer overwrite

    // Scatter the 8 product rows into buffers (buf f -> row n1(f) below).
    int kinv = 511 - tid;
    int c7 = (T == 0) ? tid : kinv;          // T=0: park[1] is row 256 @ tid
    stbuf(sRe, sIm, 0, tid,  park[0]);       // row 4T      (T=0: row 0)
    stbuf(sRe, sIm, 7, c7,   park[1]);       // row 512-4T  (T=0: row 256)
    stbuf(sRe, sIm, 1, tid,  park[2]);       // row 4T+1    (T=0: row 1)
    stbuf(sRe, sIm, 6, kinv, park[3]);       // row 511-4T  (T=0: row 511)
    stbuf(sRe, sIm, 2, tid,  park[4]);       // row 4T+2
    stbuf(sRe, sIm, 5, kinv, park[5]);       // row 510-4T
    stbuf(sRe, sIm, 3, tid,  park[6]);       // row 4T+3
    stbuf(sRe, sIm, 4, kinv, park[7]);       // row 509-4T
    __syncthreads();

    fft512<true, false, false>(sRe, sIm, sW, tid);

    // inverse inter-pass twiddle + transposed store to zB
    int f = tid & 7, k0 = tid >> 3;
    int n1;
    if (T == 0) n1 = (f < 4) ? f : (f == 7 ? 256 : 505 + f);
    else        n1 = (f < 4) ? (4 * T + f) : (505 - 4 * T + f);
    int pb = n1 * k0, ps = n1 * 64;
    float2 w  = cmul(sW[pb >> 9], sWB[pb & 511]); w.y  = -w.y;
    float2 st = cmul(sW[ps >> 9], sWB[ps & 511]); st.y = -st.y;
#pragma unroll
    for (int it = 0; it < 8; it++) {
        int k = k0 + 64 * it;
        float2 v = make_float2(sRe[f * SP + k], sIm[f * SP + k]);
        g_zB[(size_t)p * MF + k * 512 + n1] = cmul(v, w);
        w = cmul(w, st);
    }
}

// ---------------------------------------------------------------------------
extern "C" void kernel_launch(void* const* d_in, const int* in_sizes, int n_in,
                              void* d_out, int out_size) {
    const float* voice    = (const float*)d_in[0];
    const float* cpc      = (const float*)d_in[1];
    const float* amp      = (const float*)d_in[2];
    const float* rooml    = (const float*)d_in[3];
    const float* rmix     = (const float*)d_in[4];
    const float* times    = (const float*)d_in[5];
    const float* cp_items = (const float*)d_in[6];
    const float* verbs    = (const float*)d_in[7];
    const float* w1       = (const float*)d_in[8];
    const float* w2       = (const float*)d_in[9];
    const float* amaps    = (const float*)d_in[10];
    const float* decays   = (const float*)d_in[11];
    const float* gains    = (const float*)d_in[12];
    const float* mix      = (const float*)d_in[13];
    float* out = (float*)d_out;

    k_tw1<<<1, 512>>>();
    k_prep<<<64, 256>>>(voice, cpc, amp, rooml, rmix, cp_items, w1, w2, decays, gains, mix);
    k_ah<<<3072, 256>>>(amaps, verbs, times);     // h (1024) + audio (2048) blocks
    k_fft2<0><<<dim3(64, 64), 512>>>(out);        // fwd pass1 (zero-padded half skipped)
    k_fc2<<<dim3(64, 32), 512>>>();               // fwd pass2 + combine + inv pass1 -> zB
    k_fft2<3><<<dim3(64, 32), 512>>>(out);        // inv pass2 + epilogue (half outputs)
}

// round 14
// speedup vs baseline: 1.0326x; 1.0326x over previous
#include <cuda_runtime.h>
#include <math.h>

#define NS 131072           // N_SAMPLES
#define NEV 64              // B*E
#define MF 262144           // FFT length = 2*NS
#define NFRAMES 128
#define CPD 16
#define SP 588              // FFT smem buffer stride (conflict-free: 588%32=12)

struct EvScalars { int vidx; int ridx; float av0; float av1; };

__device__ EvScalars g_sc[NEV];
__device__ unsigned  g_normbits[NEV];   // max |mixed|
__device__ unsigned  g_hmaxbits[NEV];   // max |h|
__device__ int       g_vcount[8];       // events per verb
__device__ int       g_vlist[8 * 64];   // event ids grouped by verb
__device__ float     g_cpw[NEV * 3 * CPD * NFRAMES];   // smix-weighted cp_out
__device__ float     g_mixed[NEV * NS];
__device__ float     g_h[NEV * NS];
__device__ float2    g_twA[512];        // W_512^a = W_MF^(512a)
__device__ float2    g_twB[512];        // W_MF^b
// zA: forward pass-1 output (64 slots: 32 m-pairs, 32 h-pairs).
// zB: inverse pass-1 output (32 slots), layout [k*512 + n1].
__device__ float2    g_zA[NEV * MF];
__device__ float2    g_zB[NEV * MF];

// FFT output-position swizzle: value at frequency k lives at OPOS(k).
// Makes the final-stage store phase conflict-free (banks k0+8r+4*(r>>2) are
// all-distinct mod 32 over a warp) while keeping all reader phases clean.
__device__ __forceinline__ int OPOS(int k) {
    return (k & 63) + (((k >> 5) & 1) << 2) + 68 * (k >> 6);   // max 543 < SP
}

__device__ __forceinline__ float2 cmul(float2 a, float2 b) {
    return make_float2(a.x * b.x - a.y * b.y, a.x * b.y + a.y * b.x);
}
__device__ __forceinline__ float2 cadd(float2 a, float2 b){return make_float2(a.x+b.x,a.y+b.y);}
__device__ __forceinline__ float2 csub(float2 a, float2 b){return make_float2(a.x-b.x,a.y-b.y);}

template<bool INV>
__device__ __forceinline__ float2 mulj(float2 a) {  // * (-i) fwd, * (+i) inv
    return INV ? make_float2(-a.y, a.x) : make_float2(a.y, -a.x);
}

// 8-point DFT, natural-order in/out
template<bool INV>
__device__ __forceinline__ void dft8(float2 v[8]) {
    const float C = 0.70710678118654752f;
    float2 b0=cadd(v[0],v[4]), b4=csub(v[0],v[4]);
    float2 b1=cadd(v[1],v[5]), b5=csub(v[1],v[5]);
    float2 b2=cadd(v[2],v[6]), b6=csub(v[2],v[6]);
    float2 b3=cadd(v[3],v[7]), b7=csub(v[3],v[7]);
    b5 = INV ? make_float2(C*(b5.x-b5.y), C*(b5.x+b5.y))
             : make_float2(C*(b5.x+b5.y), C*(b5.y-b5.x));
    b6 = mulj<INV>(b6);
    b7 = INV ? make_float2(-C*(b7.x+b7.y), C*(b7.x-b7.y))
             : make_float2(C*(b7.y-b7.x), -C*(b7.x+b7.y));
    float2 c0=cadd(b0,b2), c2=csub(b0,b2);
    float2 c1=cadd(b1,b3), c3=mulj<INV>(csub(b1,b3));
    float2 c4=cadd(b4,b6), c6=csub(b4,b6);
    float2 c5=cadd(b5,b7), c7=mulj<INV>(csub(b5,b7));
    v[0]=cadd(c0,c1); v[4]=csub(c0,c1);
    v[2]=cadd(c2,c3); v[6]=csub(c2,c3);
    v[1]=cadd(c4,c5); v[5]=csub(c4,c5);
    v[3]=cadd(c6,c7); v[7]=csub(c6,c7);
}

// 8-point DFT with v[4..7] == 0 implicitly (zero-padded upper half). Exact.
template<bool INV>
__device__ __forceinline__ void dft8h(float2 v[8]) {
    const float C = 0.70710678118654752f;
    float2 b0=v[0], b4=v[0];
    float2 b1=v[1], b5=v[1];
    float2 b2=v[2], b6=v[2];
    float2 b3=v[3], b7=v[3];
    b5 = INV ? make_float2(C*(b5.x-b5.y), C*(b5.x+b5.y))
             : make_float2(C*(b5.x+b5.y), C*(b5.y-b5.x));
    b6 = mulj<INV>(b6);
    b7 = INV ? make_float2(-C*(b7.x+b7.y), C*(b7.x-b7.y))
             : make_float2(C*(b7.y-b7.x), -C*(b7.x+b7.y));
    float2 c0=cadd(b0,b2), c2=csub(b0,b2);
    float2 c1=cadd(b1,b3), c3=mulj<INV>(csub(b1,b3));
    float2 c4=cadd(b4,b6), c6=csub(b4,b6);
    float2 c5=cadd(b5,b7), c7=mulj<INV>(csub(b5,b7));
    v[0]=cadd(c0,c1); v[4]=csub(c0,c1);
    v[2]=cadd(c2,c3); v[6]=csub(c2,c3);
    v[1]=cadd(c4,c5); v[5]=csub(c4,c5);
    v[3]=cadd(c6,c7); v[7]=csub(c6,c7);
}

// ---------------------------------------------------------------------------
// 512-point FFT, radix-8^3, 64 threads per FFT (8 FFTs per 512-thread CTA).
// HALF: input positions 256..511 are zero. HOUT: only outputs k<256 stored.
// OUTPUT layout: frequency k at buffer position OPOS(k) (conflict-free store).
// ---------------------------------------------------------------------------
template<bool INV, bool HALF, bool HOUT>
__device__ __forceinline__ void fft512(float* sRe, float* sIm, const float2* sW, int tid) {
    int t = tid & 63;
    int base = (tid >> 6) * SP;
    float2 v[8];
    if (HALF) {
#pragma unroll
        for (int j = 0; j < 4; j++) {
            int a = base + t + 64 * j;
            v[j] = make_float2(sRe[a], sIm[a]);
        }
        dft8h<INV>(v);
    } else {
#pragma unroll
        for (int j = 0; j < 8; j++) {
            int a = base + t + 64 * j;
            v[j] = make_float2(sRe[a], sIm[a]);
        }
        dft8<INV>(v);
    }
    {
        float2 w1 = sW[t];                 // W_512^t
        if (INV) w1.y = -w1.y;
        float2 wc = w1;
        v[1] = cmul(v[1], wc);
#pragma unroll
        for (int k0 = 2; k0 < 8; k0++) { wc = cmul(wc, w1); v[k0] = cmul(v[k0], wc); }
    }
    __syncthreads();
#pragma unroll
    for (int k0 = 0; k0 < 8; k0++) {
        int a = base + 72 * k0 + t;
        sRe[a] = v[k0].x; sIm[a] = v[k0].y;
    }
    __syncthreads();
    int k0 = t >> 3, r = t & 7;
#pragma unroll
    for (int m1 = 0; m1 < 8; m1++) {
        int a = base + 72 * k0 + r + 8 * m1;
        v[m1] = make_float2(sRe[a], sIm[a]);
    }
    dft8<INV>(v);
    {
        float2 w1 = sW[8 * r];             // W_64^r
        if (INV) w1.y = -w1.y;
        float2 wc = w1;
        v[1] = cmul(v[1], wc);
#pragma unroll
        for (int k1 = 2; k1 < 8; k1++) { wc = cmul(wc, w1); v[k1] = cmul(v[k1], wc); }
    }
    __syncthreads();
#pragma unroll
    for (int k1 = 0; k1 < 8; k1++) {
        int a = base + 72 * k0 + 9 * k1 + r;
        sRe[a] = v[k1].x; sIm[a] = v[k1].y;
    }
    __syncthreads();
#pragma unroll
    for (int m0 = 0; m0 < 8; m0++) {
        int a = base + 72 * k0 + 9 * r + m0;
        v[m0] = make_float2(sRe[a], sIm[a]);
    }
    dft8<INV>(v);
    __syncthreads();
#pragma unroll
    for (int k2 = 0; k2 < (HOUT ? 4 : 8); k2++) {
        int a = base + OPOS(k0 + 8 * r + 64 * k2);
        sRe[a] = v[k2].x; sIm[a] = v[k2].y;
    }
    __syncthreads();
}

// ---------------------------------------------------------------------------
__global__ void k_tw1() {
    int t = threadIdx.x;   // 512
    double s, c;
    double angA = -2.0 * 3.14159265358979323846 * (double)t / 512.0;
    sincos(angA, &s, &c);
    g_twA[t] = make_float2((float)c, (float)s);
    double angB = -2.0 * 3.14159265358979323846 * (double)t / (double)MF;
    sincos(angB, &s, &c);
    g_twB[t] = make_float2((float)c, (float)s);
    if (t < 8) g_vcount[t] = 0;
}

// ---------------------------------------------------------------------------
// Per-event prep: argmaxes, softmaxes, cp select + sparsify (radix select),
// 3-block stack.
// ---------------------------------------------------------------------------
__global__ void k_prep(const float* __restrict__ voice, const float* __restrict__ cpc,
                       const float* __restrict__ amp,   const float* __restrict__ rooml,
                       const float* __restrict__ rmix,  const float* __restrict__ cp_items,
                       const float* __restrict__ w1,    const float* __restrict__ w2,
                       const float* __restrict__ decays,const float* __restrict__ gains,
                       const float* __restrict__ mix) {
    int e = blockIdx.x, tid = threadIdx.x;
    __shared__ float s_cp[2048];
    __shared__ float s_wc[2048];
    __shared__ float s_x[2048];
    __shared__ float s_y[2048];
    __shared__ float s_w1[256], s_w2[256];
    __shared__ float s_d[16], s_g[16];
    __shared__ float s_red[256];
    __shared__ float s_smix[3];
    __shared__ int   s_vidx, s_cidx;
    __shared__ int   s_hist[256];
    __shared__ unsigned s_pref;
    __shared__ int   s_rem;

    if (tid == 0) {
        const float* v = voice + e * 8;
        int vi = 0; float bv = v[0];
        for (int i = 1; i < 8; i++) if (v[i] > bv) { bv = v[i]; vi = i; }
        s_vidx = vi;
        const float* c = cpc + e * 512;
        int ci = 0; float bc = c[0];
        for (int i = 1; i < 512; i++) if (c[i] > bc) { bc = c[i]; ci = i; }
        s_cidx = ci;
        const float* r = rooml + e * 8;
        int ri = 0; float br = r[0];
        for (int i = 1; i < 8; i++) if (r[i] > br) { br = r[i]; ri = i; }
        float m0 = rmix[e * 2 + 0], m1 = rmix[e * 2 + 1];
        float mx = fmaxf(m0, m1);
        float e0 = expf(m0 - mx), e1 = expf(m1 - mx);
        float vm0 = e0 / (e0 + e1), vm1 = e1 / (e0 + e1);
        float a = fabsf(amp[e]);
        g_sc[e].vidx = vi; g_sc[e].ridx = ri;
        g_sc[e].av0 = a * vm0; g_sc[e].av1 = a * vm1;
        int pos = atomicAdd(&g_vcount[ri], 1);
        g_vlist[ri * 64 + pos] = e;
        float q0 = mix[vi * 3 + 0], q1 = mix[vi * 3 + 1], q2 = mix[vi * 3 + 2];
        float qm = fmaxf(q0, fmaxf(q1, q2));
        float f0 = expf(q0 - qm), f1 = expf(q1 - qm), f2 = expf(q2 - qm);
        float fs = f0 + f1 + f2;
        s_smix[0] = f0 / fs; s_smix[1] = f1 / fs; s_smix[2] = f2 / fs;
        g_normbits[e] = 0u;
        g_hmaxbits[e] = 0u;
        s_pref = 0u; s_rem = 31;
    }
    __syncthreads();
    int vi = s_vidx, ci = s_cidx;

    float ls = 0.f;
    for (int i = tid; i < 2048; i += 256) {
        float v = cp_items[ci * 2048 + i];
        s_cp[i] = v; ls += v;
    }
    s_red[tid] = ls; __syncthreads();
    for (int o = 128; o > 0; o >>= 1) {
        if (tid < o) s_red[tid] += s_red[tid + o];
        __syncthreads();
    }
    float inv = 1.0f / (s_red[0] + 1e-8f);

    // Radix-select V32 = 32nd-largest value (uint keys monotone; values > 0).
    float vloc[8]; unsigned keys[8];
#pragma unroll
    for (int u = 0; u < 8; u++) {
        vloc[u] = s_cp[tid + 256 * u];
        keys[u] = __float_as_uint(vloc[u]);
    }
#pragma unroll
    for (int pass = 0; pass < 4; pass++) {
        int shift = 24 - 8 * pass;
        unsigned mhi = (pass == 0) ? 0u : (0xFFFFFFFFu << (32 - 8 * pass));
        s_hist[tid] = 0;
        __syncthreads();
        unsigned pref = s_pref;
#pragma unroll
        for (int u = 0; u < 8; u++)
            if ((keys[u] & mhi) == pref)
                atomicAdd(&s_hist[(keys[u] >> shift) & 0xFF], 1);
        __syncthreads();
        int rem = s_rem;
        int above = 0;
        for (int b = tid + 1; b < 256; b++) above += s_hist[b];
        if (above <= rem && rem < above + s_hist[tid]) {
            s_pref = pref | ((unsigned)tid << shift);
            s_rem = rem - above;
        }
        __syncthreads();
    }
    unsigned kth = s_pref;
#pragma unroll
    for (int u = 0; u < 8; u++)
        s_wc[tid + 256 * u] = (keys[u] >= kth) ? vloc[u] * inv : 0.f;
    __syncthreads();

    for (int blk = 0; blk < 3; blk++) {
        s_w1[tid] = w1[(vi * 3 + blk) * 256 + tid];
        s_w2[tid] = w2[(vi * 3 + blk) * 256 + tid];
        if (tid < 16) {
            float dp = decays[(vi * 3 + blk) * 16 + tid];
            s_d[tid] = 0.5f + (1.f / (1.f + expf(-dp))) * 0.5f;
            float gp = gains[(vi * 3 + blk) * 16 + tid];
            s_g[tid] = (1.f / (1.f + expf(-gp))) * 5.f;
        }
        __syncthreads();
#pragma unroll
        for (int u = 0; u < 8; u++) {
            int idx = tid + 256 * u;
            int c = idx >> 7, f = idx & 127;
            float acc = 0.f;
#pragma unroll
            for (int k = 0; k < 16; k++)
                acc += s_w1[c * 16 + k] * fmaxf(s_wc[k * 128 + f], 0.f);
            s_x[idx] = acc;
        }
        __syncthreads();
        if (tid < 16) {
            float d = s_d[tid];
            float y = 0.f;
            for (int f = 0; f < 128; f++) {
                y = d * (s_x[tid * 128 + f] + y);
                s_y[tid * 128 + f] = y;
            }
        }
        __syncthreads();
#pragma unroll
        for (int u = 0; u < 8; u++) {
            int idx = tid + 256 * u;
            int c = idx >> 7, f = idx & 127;
            float acc = s_x[idx];
#pragma unroll
            for (int k = 0; k < 16; k++)
                acc += s_w2[c * 16 + k] * s_y[k * 128 + f];
            float co = tanhf(acc * s_g[c]);
            g_cpw[((e * 3 + blk) * 16 + c) * 128 + f] = s_smix[blk] * co;
            s_wc[idx] = co;
        }
        __syncthreads();
    }
}

// ---------------------------------------------------------------------------
// MERGED audio-synthesis + h-computation kernel (flat grid, 2048 blocks).
//   bid < 1024 : h path (chunk = bid&127, verb = bid>>7), float4 verb loads
//   bid >= 1024: audio path (fg = (bid-1024)&15, e = (bid-1024)>>4)
// ---------------------------------------------------------------------------
__global__ void __launch_bounds__(256, 3) k_ah(const float* __restrict__ audio_maps,
                                               const float* __restrict__ verbs,
                                               const float* __restrict__ times) {
    int bid = blockIdx.x, tid = threadIdx.x;
    __shared__ float s_c[8][48];
    __shared__ float s_red[256];
    __shared__ int s_v;
    __shared__ float s_t[8][128];
    __shared__ int   s_ei[8];
    __shared__ float s_av0[8], s_av1[8];
    __shared__ float s_wm[8][8];

    if (bid < 1024) {
        // ------------- h path -------------
        int chunk = bid & 127, r = bid >> 7;
        int cnt = g_vcount[r];
        if (cnt == 0) return;
        int t0 = chunk << 10;
        const float* vb = verbs + (size_t)r * NS;

        for (int b = 0; b < cnt; b += 8) {
            int nb = min(8, cnt - b);
            if (tid < 8) {
                if (tid < nb) {
                    int e = g_vlist[r * 64 + b + tid];
                    s_ei[tid] = e;
                    s_av0[tid] = g_sc[e].av0;
                    s_av1[tid] = g_sc[e].av1;
                } else s_ei[tid] = -1;
            }
            __syncthreads();
            for (int s = tid; s < 1024; s += 256) {
                int i = s >> 7, f = s & 127;
                s_t[i][f] = (i < nb) ? times[(size_t)g_vlist[r * 64 + b + i] * 128 + f] : 0.f;
            }
            __syncthreads();

            float4 acc[8];
#pragma unroll
            for (int i = 0; i < 8; i++) acc[i] = make_float4(0.f, 0.f, 0.f, 0.f);
            const float4* vbase = reinterpret_cast<const float4*>(vb + t0) + tid;
#pragma unroll 2
            for (int f = 0; f <= chunk; f++) {
                float4 v = vbase[-(f << 8)];
#pragma unroll
                for (int i = 0; i < 8; i++) {
                    float tf = s_t[i][f];
                    acc[i].x += v.x * tf; acc[i].y += v.y * tf;
                    acc[i].z += v.z * tf; acc[i].w += v.w * tf;
                }
            }

            float lm[8];
#pragma unroll
            for (int i = 0; i < 8; i++) lm[i] = 0.f;
            for (int i = 0; i < nb; i++) {
                float a0 = s_av0[i];
                float4 val = make_float4(a0 * acc[i].x, a0 * acc[i].y,
                                         a0 * acc[i].z, a0 * acc[i].w);
                if (tid == 0) val.x += s_av1[i] * s_t[i][chunk];
                reinterpret_cast<float4*>(g_h + (size_t)s_ei[i] * NS + t0)[tid] = val;
                lm[i] = fmaxf(fmaxf(fabsf(val.x), fabsf(val.y)),
                              fmaxf(fabsf(val.z), fabsf(val.w)));
            }
#pragma unroll
            for (int i = 0; i < 8; i++) {
#pragma unroll
                for (int off = 16; off; off >>= 1)
                    lm[i] = fmaxf(lm[i], __shfl_xor_sync(0xffffffffu, lm[i], off));
            }
            int wid = tid >> 5, lane = tid & 31;
            if (lane == 0) {
#pragma unroll
                for (int i = 0; i < 8; i++) s_wm[wid][i] = lm[i];
            }
            __syncthreads();
            if (tid < 8) {
                float m = s_wm[0][tid];
#pragma unroll
                for (int w = 1; w < 8; w++) m = fmaxf(m, s_wm[w][tid]);
                if (tid < nb) atomicMax(&g_hmaxbits[s_ei[tid]], __float_as_uint(m));
            }
            __syncthreads();
        }
    } else {
        // ------------- audio path -------------
        int bid2 = bid - 1024;
        int fg = bid2 & 15, e = bid2 >> 4;
        if (tid == 0) s_v = g_sc[e].vidx;
        for (int s = tid; s < 384; s += 256) {
            int fr = s / 48, ic = s % 48;
            int i = ic >> 4, c = ic & 15;
            s_c[fr][ic] = g_cpw[((e * 3 + i) * 16 + c) * 128 + (fg * 8 + fr)];
        }
        __syncthreads();
        const float* am = audio_maps + (size_t)s_v * 3 * 1024 * 16;
        float acc[8][4];
#pragma unroll
        for (int fr = 0; fr < 8; fr++)
#pragma unroll
            for (int q = 0; q < 4; q++) acc[fr][q] = 0.f;

#pragma unroll
        for (int i = 0; i < 3; i++) {
#pragma unroll
            for (int r = 0; r < 4; r++) {
                float4 a[4];
#pragma unroll
                for (int q = 0; q < 4; q++)
                    a[q] = __ldg(reinterpret_cast<const float4*>(
                               am + (i * 1024 + tid + 256 * q) * 16) + r);
#pragma unroll
                for (int fr = 0; fr < 8; fr++) {
                    float c0 = s_c[fr][i * 16 + 4 * r + 0];
                    float c1 = s_c[fr][i * 16 + 4 * r + 1];
                    float c2 = s_c[fr][i * 16 + 4 * r + 2];
                    float c3 = s_c[fr][i * 16 + 4 * r + 3];
#pragma unroll
                    for (int q = 0; q < 4; q++)
                        acc[fr][q] += a[q].x * c0 + a[q].y * c1 + a[q].z * c2 + a[q].w * c3;
                }
            }
        }
        float lmax = 0.f;
#pragma unroll
        for (int fr = 0; fr < 8; fr++) {
#pragma unroll
            for (int q = 0; q < 4; q++) {
                float v = acc[fr][q];
                g_mixed[e * NS + (fg * 8 + fr) * 1024 + tid + 256 * q] = v;
                lmax = fmaxf(lmax, fabsf(v));
            }
        }
        s_red[tid] = lmax; __syncthreads();
        for (int o = 128; o > 0; o >>= 1) {
            if (tid < o) s_red[tid] = fmaxf(s_red[tid], s_red[tid + o]);
            __syncthreads();
        }
        if (tid == 0) atomicMax(&g_normbits[e], __float_as_uint(s_red[0]));
    }
}

// ---------------------------------------------------------------------------
// FFT passes. MODE 0: fwd pass1 (64 slots) -> zA (HALF: zero-padded top).
// MODE 3: inv pass2 + epilogue (HOUT: only k<256 outputs stored/needed).
// ---------------------------------------------------------------------------
template <int MODE>
__global__ void __launch_bounds__(512) k_fft2(float* __restrict__ out) {
    __shared__ float sRe[8 * SP];
    __shared__ float sIm[8 * SP];
    __shared__ float2 sW[512];
    __shared__ float2 sWB[512];
    int slot = blockIdx.y, tile = blockIdx.x, tid = threadIdx.x;
    int c0 = tile * 8;
    const bool INV = (MODE >= 2);

    sW[tid] = g_twA[tid];
    if (MODE == 0) sWB[tid] = g_twB[tid];

    if (MODE == 0) {
        const float *s1, *s2;
        float f1, f2;
        if (slot < 32) {
            int e1 = 2 * slot, e2 = 2 * slot + 1;
            s1 = g_mixed + (size_t)e1 * NS;
            s2 = g_mixed + (size_t)e2 * NS;
            f1 = 1.0f / (__uint_as_float(g_normbits[e1]) + 1e-8f);
            f2 = 1.0f / (__uint_as_float(g_normbits[e2]) + 1e-8f);
        } else {
            int e1 = 2 * (slot - 32), e2 = e1 + 1;
            s1 = g_h + (size_t)e1 * NS;
            s2 = g_h + (size_t)e2 * NS;
            f1 = 1.0f / (__uint_as_float(g_hmaxbits[e1]) + 1e-20f);
            f2 = 1.0f / (__uint_as_float(g_hmaxbits[e2]) + 1e-20f);
        }
#pragma unroll
        for (int it = 0; it < 4; it++) {
            int lin = tid + 512 * it;
            int f = lin & 7, r = lin >> 3;          // r < 256
            int n = c0 + f + 512 * r;               // n < NS always
            sRe[f * SP + r] = s1[n] * f1;
            sIm[f * SP + r] = s2[n] * f2;
        }
    } else {   // MODE 3: rows of zB, contiguous
#pragma unroll
        for (int it = 0; it < 8; it++) {
            int lin = tid + 512 * it;
            int f = lin >> 9, n1 = lin & 511;
            float2 z = g_zB[(size_t)slot * MF + (c0 + f) * 512 + n1];
            sRe[f * SP + n1] = z.x; sIm[f * SP + n1] = z.y;
        }
    }
    __syncthreads();

    fft512<INV, MODE == 0, MODE == 3>(sRe, sIm, sW, tid);

    if (MODE == 0) {
        int f = tid & 7, k0 = tid >> 3;
        int n1 = c0 + f;
        int pb = n1 * k0;
        int ps = n1 * 64;
        float2 w  = cmul(sW[pb >> 9], sWB[pb & 511]);   // W_MF^(n1*k0)
        float2 st = cmul(sW[ps >> 9], sWB[ps & 511]);   // W_MF^(n1*64)
        int kb = k0 + (((k0 >> 5) & 1) << 2);           // OPOS(k0+64it) = kb+68it
#pragma unroll
        for (int it = 0; it < 8; it++) {
            int k = k0 + 64 * it;
            int a = f * SP + kb + 68 * it;
            float2 v = make_float2(sRe[a], sIm[a]);
            g_zA[(size_t)slot * MF + k * 512 + n1] = cmul(v, w);
            w = cmul(w, st);
        }
    } else {
        int e1 = 2 * slot, e2 = 2 * slot + 1;
        const float invm = 1.0f / (float)MF;
        float sc1 = (__uint_as_float(g_hmaxbits[e1]) + 1e-20f) * invm;
        float sc2 = (__uint_as_float(g_hmaxbits[e2]) + 1e-20f) * invm;
        float* o1 = out + (size_t)e1 * NS;
        float* o2 = out + (size_t)e2 * NS;
#pragma unroll
        for (int it = 0; it < 4; it++) {   // only k < 256 -> t < NS
            int lin = tid + 512 * it;
            int f = lin & 7, k = lin >> 3;
            int t = (c0 + f) + 512 * k;
            int a = f * SP + OPOS(k);
            o1[t] = sRe[a] * sc1;
            o2[t] = sIm[a] * sc2;
        }
    }
}

// ---------------------------------------------------------------------------
// Fused forward pass-2 + combine + INVERSE pass-1 (SP pad, staged twB).
// All reads of fft512 output go through OPOS(k).
// ---------------------------------------------------------------------------
__device__ __forceinline__ float2 ldbuf(const float* sRe, const float* sIm, int i, int k) {
    int a = i * SP + OPOS(k);
    return make_float2(sRe[a], sIm[a]);
}
__device__ __forceinline__ void stbuf(float* sRe, float* sIm, int i, int k, float2 v) {
    sRe[i * SP + k] = v.x; sIm[i * SP + k] = v.y;   // plain: inverse-FFT input
}

__global__ void __launch_bounds__(512, 2) k_fc2() {
    __shared__ float sRe[8 * SP];
    __shared__ float sIm[8 * SP];
    __shared__ float2 sW[512];
    __shared__ float2 sWB[512];
    int p = blockIdx.y, T = blockIdx.x, tid = threadIdx.x;
    sW[tid] = g_twA[tid];
    sWB[tid] = g_twB[tid];

    float2 park[8];

#pragma unroll
    for (int half = 0; half < 2; half++) {
        int t = 2 * T + half;
        int rows4[4];
        if (t == 0) { rows4[0] = 0; rows4[1] = 256; rows4[2] = 1; rows4[3] = 511; }
        else { rows4[0] = 2 * t; rows4[1] = 512 - 2 * t;
               rows4[2] = 2 * t + 1; rows4[3] = 511 - 2 * t; }
        if (half) __syncthreads();    // half0 product reads complete before overwrite
#pragma unroll
        for (int it = 0; it < 8; it++) {
            int sl = (it < 4) ? p : (32 + p);
            float2 z = g_zA[(size_t)sl * MF + rows4[it & 3] * 512 + tid];
            sRe[it * SP + tid] = z.x; sIm[it * SP + tid] = z.y;
        }
        __syncthreads();

        fft512<false, false, false>(sRe, sIm, sW, tid);

        int o = half * 4;
        if (t == 0) {
            {   // row 0 (self-mirror: col (512-k2)&511)
                int kp = (512 - tid) & 511;
                float2 Za = ldbuf(sRe, sIm, 0, tid), Zb = ldbuf(sRe, sIm, 0, kp);
                float2 Ha = ldbuf(sRe, sIm, 4, tid), Hb = ldbuf(sRe, sIm, 4, kp);
                float2 M1 = make_float2(0.5f*(Za.x+Zb.x), 0.5f*(Za.y-Zb.y));
                float2 M2 = make_float2(0.5f*(Za.y+Zb.y), 0.5f*(Zb.x-Za.x));
                float2 H1 = make_float2(0.5f*(Ha.x+Hb.x), 0.5f*(Ha.y-Hb.y));
                float2 H2 = make_float2(0.5f*(Ha.y+Hb.y), 0.5f*(Hb.x-Ha.x));
                float2 P1 = cmul(M1, H1), P2 = cmul(M2, H2);
                park[o + 0] = make_float2(P1.x - P2.y, P1.y + P2.x);   // row 0 @ tid
            }
            {   // row 256 (self-mirror: col 511-k2)
                int kp = 511 - tid;
                float2 Za = ldbuf(sRe, sIm, 1, tid), Zb = ldbuf(sRe, sIm, 1, kp);
                float2 Ha = ldbuf(sRe, sIm, 5, tid), Hb = ldbuf(sRe, sIm, 5, kp);
                float2 M1 = make_float2(0.5f*(Za.x+Zb.x), 0.5f*(Za.y-Zb.y));
                float2 M2 = make_float2(0.5f*(Za.y+Zb.y), 0.5f*(Zb.x-Za.x));
                float2 H1 = make_float2(0.5f*(Ha.x+Hb.x), 0.5f*(Ha.y-Hb.y));
                float2 H2 = make_float2(0.5f*(Ha.y+Hb.y), 0.5f*(Hb.x-Ha.x));
                float2 P1 = cmul(M1, H1), P2 = cmul(M2, H2);
                park[o + 1] = make_float2(P1.x - P2.y, P1.y + P2.x);   // row 256 @ tid
            }
            {   // pair (1, 511)
                int kp = 511 - tid;
                float2 Za = ldbuf(sRe, sIm, 2, tid), Zb = ldbuf(sRe, sIm, 3, kp);
                float2 Ha = ldbuf(sRe, sIm, 6, tid), Hb = ldbuf(sRe, sIm, 7, kp);
                float2 M1 = make_float2(0.5f*(Za.x+Zb.x), 0.5f*(Za.y-Zb.y));
                float2 M2 = make_float2(0.5f*(Za.y+Zb.y), 0.5f*(Zb.x-Za.x));
                float2 H1 = make_float2(0.5f*(Ha.x+Hb.x), 0.5f*(Ha.y-Hb.y));
                float2 H2 = make_float2(0.5f*(Ha.y+Hb.y), 0.5f*(Hb.x-Ha.x));
                float2 P1 = cmul(M1, H1), P2 = cmul(M2, H2);
                park[o + 2] = make_float2(P1.x - P2.y, P1.y + P2.x);   // row 1 @ tid
                park[o + 3] = make_float2(P1.x + P2.y, P2.x - P1.y);   // row 511 @ 511-tid
            }
        } else {
#pragma unroll
            for (int pr = 0; pr < 2; pr++) {
                int ia = 2 * pr, ib = 2 * pr + 1;
                int kp = 511 - tid;
                float2 Za = ldbuf(sRe, sIm, ia, tid), Zb = ldbuf(sRe, sIm, ib, kp);
                float2 Ha = ldbuf(sRe, sIm, ia + 4, tid), Hb = ldbuf(sRe, sIm, ib + 4, kp);
                float2 M1 = make_float2(0.5f*(Za.x+Zb.x), 0.5f*(Za.y-Zb.y));
                float2 M2 = make_float2(0.5f*(Za.y+Zb.y), 0.5f*(Zb.x-Za.x));
                float2 H1 = make_float2(0.5f*(Ha.x+Hb.x), 0.5f*(Ha.y-Hb.y));
                float2 H2 = make_float2(0.5f*(Ha.y+Hb.y), 0.5f*(Hb.x-Ha.x));
                float2 P1 = cmul(M1, H1), P2 = cmul(M2, H2);
                park[o + 2 * pr + 0] = make_float2(P1.x - P2.y, P1.y + P2.x);  // rows4[ia] @ tid
                park[o + 2 * pr + 1] = make_float2(P1.x + P2.y, P2.x - P1.y);  // rows4[ib] @ 511-tid
            }
        }
    }
    __syncthreads();   // all product reads done before buffer overwrite

    // Scatter the 8 product rows into buffers (buf f -> row n1(f) below).
    int kinv = 511 - tid;
    int c7 = (T == 0) ? tid : kinv;          // T=0: park[1] is row 256 @ tid
    stbuf(sRe, sIm, 0, tid,  park[0]);       // row 4T      (T=0: row 0)
    stbuf(sRe, sIm, 7, c7,   park[1]);       // row 512-4T  (T=0: row 256)
    stbuf(sRe, sIm, 1, tid,  park[2]);       // row 4T+1    (T=0: row 1)
    stbuf(sRe, sIm, 6, kinv, park[3]);       // row 511-4T  (T=0: row 511)
    stbuf(sRe, sIm, 2, tid,  park[4]);       // row 4T+2
    stbuf(sRe, sIm, 5, kinv, park[5]);       // row 510-4T
    stbuf(sRe, sIm, 3, tid,  park[6]);       // row 4T+3
    stbuf(sRe, sIm, 4, kinv, park[7]);       // row 509-4T
    __syncthreads();

    fft512<true, false, false>(sRe, sIm, sW, tid);

    // inverse inter-pass twiddle + transposed store to zB
    int f = tid & 7, k0 = tid >> 3;
    int n1;
    if (T == 0) n1 = (f < 4) ? f : (f == 7 ? 256 : 505 + f);
    else        n1 = (f < 4) ? (4 * T + f) : (505 - 4 * T + f);
    int pb = n1 * k0, ps = n1 * 64;
    float2 w  = cmul(sW[pb >> 9], sWB[pb & 511]); w.y  = -w.y;
    float2 st = cmul(sW[ps >> 9], sWB[ps & 511]); st.y = -st.y;
    int kb = k0 + (((k0 >> 5) & 1) << 2);         // OPOS(k0+64it) = kb+68it
#pragma unroll
    for (int it = 0; it < 8; it++) {
        int k = k0 + 64 * it;
        int a = f * SP + kb + 68 * it;
        float2 v = make_float2(sRe[a], sIm[a]);
        g_zB[(size_t)p * MF + k * 512 + n1] = cmul(v, w);
        w = cmul(w, st);
    }
}

// ---------------------------------------------------------------------------
extern "C" void kernel_launch(void* const* d_in, const int* in_sizes, int n_in,
                              void* d_out, int out_size) {
    const float* voice    = (const float*)d_in[0];
    const float* cpc      = (const float*)d_in[1];
    const float* amp      = (const float*)d_in[2];
    const float* rooml    = (const float*)d_in[3];
    const float* rmix     = (const float*)d_in[4];
    const float* times    = (const float*)d_in[5];
    const float* cp_items = (const float*)d_in[6];
    const float* verbs    = (const float*)d_in[7];
    const float* w1       = (const float*)d_in[8];
    const float* w2       = (const float*)d_in[9];
    const float* amaps    = (const float*)d_in[10];
    const float* decays   = (const float*)d_in[11];
    const float* gains    = (const float*)d_in[12];
    const float* mix      = (const float*)d_in[13];
    float* out = (float*)d_out;

    k_tw1<<<1, 512>>>();
    k_prep<<<64, 256>>>(voice, cpc, amp, rooml, rmix, cp_items, w1, w2, decays, gains, mix);
    k_ah<<<2048, 256>>>(amaps, verbs, times);     // h (1024) + audio (1024) blocks
    k_fft2<0><<<dim3(64, 64), 512>>>(out);        // fwd pass1 (zero-padded half skipped)
    k_fc2<<<dim3(64, 32), 512>>>();               // fwd pass2 + combine + inv pass1 -> zB
    k_fft2<3><<<dim3(64, 32), 512>>>(out);        // inv pass2 + epilogue (half outputs)
}